// round 6
// baseline (speedup 1.0000x reference)
#include <cuda_runtime.h>
#include <cstddef>
#include <cstdint>

#define EPS 1e-8f

static constexpr int B    = 1024;
static constexpr int K    = 512;
static constexpr int E    = 64;
static constexpr int D    = 769;
static constexpr int TOPK = 64;

__device__ float g_aw[B * E];      // normalized anchor weights a
__device__ float g_la[B * E];      // log(a + EPS) via XLA-CPU log

// ---------------------------------------------------------------------------
// Bit-exact replica of XLA-CPU's GenerateVF32Log (Eigen plog / Cephes):
// NO FMA contraction, exact operation order. DO NOT MODIFY.
// ---------------------------------------------------------------------------
__device__ __forceinline__ float xla_logf(float xin) {
    float x = fmaxf(xin, __uint_as_float(0x00800000u));
    uint32_t bits = __float_as_uint(x);
    int emm0 = (int)(bits >> 23) - 126;
    float e = (float)emm0;
    float m = __uint_as_float((bits & 0x807fffffu) | 0x3f000000u);
    bool mask = m < __uint_as_float(0x3f3504f3u);
    float tmp = mask ? m : 0.0f;
    float xx = __fadd_rn(__fsub_rn(m, 1.0f), tmp);
    e = __fsub_rn(e, mask ? 1.0f : 0.0f);

    float z = __fmul_rn(xx, xx);
    float y = 7.0376836292e-2f;
    y = __fadd_rn(__fmul_rn(y, xx), -1.1514610310e-1f);
    y = __fadd_rn(__fmul_rn(y, xx),  1.1676998740e-1f);
    y = __fadd_rn(__fmul_rn(y, xx), -1.2420140846e-1f);
    y = __fadd_rn(__fmul_rn(y, xx),  1.4249322787e-1f);
    y = __fadd_rn(__fmul_rn(y, xx), -1.6668057665e-1f);
    y = __fadd_rn(__fmul_rn(y, xx),  2.0000714765e-1f);
    y = __fadd_rn(__fmul_rn(y, xx), -2.4999993993e-1f);
    y = __fadd_rn(__fmul_rn(y, xx),  3.3333331174e-1f);
    y = __fmul_rn(y, xx);
    y = __fmul_rn(y, z);
    y = __fadd_rn(y, __fmul_rn(e, -2.12194440e-4f));
    y = __fsub_rn(y, __fmul_rn(z, 0.5f));
    float r = __fadd_rn(xx, y);
    r = __fadd_rn(r, __fmul_rn(e, 0.693359375f));
    return r;
}

#define NEON_HORIZ(a0, a1, a2, a3) __fadd_rn(__fadd_rn(a0, a2), __fadd_rn(a1, a3))

// ---------------------------------------------------------------------------
// K1: anchor rows. One thread per b, XLA-CPU op order. (unchanged from R5)
// ---------------------------------------------------------------------------
__global__ __launch_bounds__(256) void k_anchor(const float* __restrict__ anchor) {
    int b = blockIdx.x * blockDim.x + threadIdx.x;
    if (b >= B) return;
    const float4* row = (const float4*)(anchor + b * E);
    float4 vv[16];
    float a0 = 0.f, a1 = 0.f, a2 = 0.f, a3 = 0.f;
    #pragma unroll
    for (int c = 0; c < 16; c++) {
        vv[c] = __ldg(row + c);
        a0 = __fadd_rn(a0, __fadd_rn(vv[c].x, EPS));
        a1 = __fadd_rn(a1, __fadd_rn(vv[c].y, EPS));
        a2 = __fadd_rn(a2, __fadd_rn(vv[c].z, EPS));
        a3 = __fadd_rn(a3, __fadd_rn(vv[c].w, EPS));
    }
    float S = NEON_HORIZ(a0, a1, a2, a3);
    const float* vf = (const float*)vv;
    #pragma unroll
    for (int e = 0; e < E; e++) {
        float a = __fdiv_rn(__fadd_rn(vf[e], EPS), S);
        g_aw[b * E + e] = a;
        g_la[b * E + e] = xla_logf(__fadd_rn(a, EPS));
    }
}

// ---------------------------------------------------------------------------
// K2 (fused): per batch row — scores (512 candidates), bitonic top-64,
// gather of the 64 selected 769-float rows, score output.
// One CTA of 512 threads per b. Score arithmetic is op-identical to the
// passing R5 kernel. Two-pass row read (asm load breaks CSE) keeps registers
// low for >=2 CTAs/SM so gather (DRAM) overlaps scores (FMA) across CTAs.
// ---------------------------------------------------------------------------
__global__ __launch_bounds__(512, 2) void k_fused(
    const float* __restrict__ neg, const float* __restrict__ cand,
    float* __restrict__ out_hard, float* __restrict__ out_scores)
{
    __shared__ float s_a[E], s_la[E];
    __shared__ float ss[K];
    __shared__ int   si[K];

    int b   = blockIdx.x;
    int tid = threadIdx.x;
    if (tid < E) {
        s_a[tid]  = g_aw[b * E + tid];
        s_la[tid] = g_la[b * E + tid];
    }
    __syncthreads();

    // ---- Phase 1: score for candidate k = tid --------------------------
    const float4* row = (const float4*)(neg + ((size_t)b * K + tid) * E);

    // pass 1: row sum (4 NEON accumulators). asm volatile loads so the
    // compiler cannot CSE them with pass-2 loads (keeps regs low).
    float a0 = 0.f, a1 = 0.f, a2 = 0.f, a3 = 0.f;
    #pragma unroll
    for (int c = 0; c < 16; c++) {
        float4 v;
        asm volatile("ld.global.nc.v4.f32 {%0,%1,%2,%3}, [%4];"
                     : "=f"(v.x), "=f"(v.y), "=f"(v.z), "=f"(v.w)
                     : "l"(row + c));
        a0 = __fadd_rn(a0, __fadd_rn(v.x, EPS));
        a1 = __fadd_rn(a1, __fadd_rn(v.y, EPS));
        a2 = __fadd_rn(a2, __fadd_rn(v.z, EPS));
        a3 = __fadd_rn(a3, __fadd_rn(v.w, EPS));
    }
    float S = NEON_HORIZ(a0, a1, a2, a3);

    // pass 2: normalized-log KL terms (rows are L2-resident on re-read)
    float k0 = 0.f, k1 = 0.f, k2 = 0.f, k3 = 0.f;
    #pragma unroll 4
    for (int c = 0; c < 16; c++) {
        float4 v = __ldg(row + c);
        const float* vf = (const float*)&v;
        #pragma unroll
        for (int j = 0; j < 4; j++) {
            int e = 4 * c + j;
            float nn = __fdiv_rn(__fadd_rn(vf[j], EPS), S);
            float ln = xla_logf(__fadd_rn(nn, EPS));
            float t  = __fmul_rn(s_a[e], __fsub_rn(s_la[e], ln));
            if (j == 0) k0 = __fadd_rn(k0, t);
            if (j == 1) k1 = __fadd_rn(k1, t);
            if (j == 2) k2 = __fadd_rn(k2, t);
            if (j == 3) k3 = __fadd_rn(k3, t);
        }
    }
    ss[tid] = -NEON_HORIZ(k0, k1, k2, k3);
    si[tid] = tid;

    // ---- Phase 2: bitonic sort of 512 (desc, ties -> lower index) ------
    for (int sz = 2; sz <= K; sz <<= 1) {
        for (int j = sz >> 1; j > 0; j >>= 1) {
            __syncthreads();
            int ixj = tid ^ j;
            if (ixj > tid) {
                bool desc = ((tid & sz) == 0);
                float s1 = ss[tid], s2 = ss[ixj];
                int   i1 = si[tid], i2 = si[ixj];
                bool g = (s1 > s2) || (s1 == s2 && i1 < i2);
                if (g != desc) {
                    ss[tid] = s2; ss[ixj] = s1;
                    si[tid] = i2; si[ixj] = i1;
                }
            }
        }
    }
    __syncthreads();

    // ---- Phase 3: emit scores + gather hard negatives ------------------
    if (tid < TOPK) out_scores[b * TOPK + tid] = ss[tid];

    int warp = tid >> 5, lane = tid & 31;
    #pragma unroll
    for (int j = warp; j < TOPK; j += 16) {
        int idx = si[j];
        const float* __restrict__ src = cand + ((size_t)b * K + idx) * D;
        float* __restrict__ dst = out_hard + ((size_t)b * TOPK + j) * D;
        #pragma unroll 4
        for (int i = lane; i < D; i += 32)
            dst[i] = __ldg(src + i);
    }
}

// ---------------------------------------------------------------------------
extern "C" void kernel_launch(void* const* d_in, const int* in_sizes, int n_in,
                              void* d_out, int out_size) {
    const float* anchor = (const float*)d_in[0];  // (B, E)
    const float* neg    = (const float*)d_in[1];  // (B, K, E)
    const float* cand   = (const float*)d_in[2];  // (B, K, D)
    float* out        = (float*)d_out;
    float* out_hard   = out;                          // (B, TOPK, D)
    float* out_scores = out + (size_t)B * TOPK * D;   // (B, TOPK)

    k_anchor<<<4, 256>>>(anchor);
    k_fused<<<B, 512>>>(neg, cand, out_hard, out_scores);
}

// round 7
// speedup vs baseline: 1.0744x; 1.0744x over previous
#include <cuda_runtime.h>
#include <cstddef>
#include <cstdint>

#define EPS 1e-8f

static constexpr int B    = 1024;
static constexpr int K    = 512;
static constexpr int E    = 64;
static constexpr int D    = 769;
static constexpr int TOPK = 64;

__device__ float g_aw[B * E];      // normalized anchor weights a
__device__ float g_la[B * E];      // log(a + EPS) via XLA-CPU log
__device__ float g_scores[B * K];
__device__ int   g_idx[B * TOPK];

// ---------------------------------------------------------------------------
// Bit-exact replica of XLA-CPU's GenerateVF32Log (Eigen plog / Cephes):
// NO FMA contraction, exact operation order. DO NOT MODIFY.
// ---------------------------------------------------------------------------
__device__ __forceinline__ float xla_logf(float xin) {
    float x = fmaxf(xin, __uint_as_float(0x00800000u));
    uint32_t bits = __float_as_uint(x);
    int emm0 = (int)(bits >> 23) - 126;
    float e = (float)emm0;
    float m = __uint_as_float((bits & 0x807fffffu) | 0x3f000000u);
    bool mask = m < __uint_as_float(0x3f3504f3u);
    float tmp = mask ? m : 0.0f;
    float xx = __fadd_rn(__fsub_rn(m, 1.0f), tmp);
    e = __fsub_rn(e, mask ? 1.0f : 0.0f);

    float z = __fmul_rn(xx, xx);
    float y = 7.0376836292e-2f;
    y = __fadd_rn(__fmul_rn(y, xx), -1.1514610310e-1f);
    y = __fadd_rn(__fmul_rn(y, xx),  1.1676998740e-1f);
    y = __fadd_rn(__fmul_rn(y, xx), -1.2420140846e-1f);
    y = __fadd_rn(__fmul_rn(y, xx),  1.4249322787e-1f);
    y = __fadd_rn(__fmul_rn(y, xx), -1.6668057665e-1f);
    y = __fadd_rn(__fmul_rn(y, xx),  2.0000714765e-1f);
    y = __fadd_rn(__fmul_rn(y, xx), -2.4999993993e-1f);
    y = __fadd_rn(__fmul_rn(y, xx),  3.3333331174e-1f);
    y = __fmul_rn(y, xx);
    y = __fmul_rn(y, z);
    y = __fadd_rn(y, __fmul_rn(e, -2.12194440e-4f));
    y = __fsub_rn(y, __fmul_rn(z, 0.5f));
    float r = __fadd_rn(xx, y);
    r = __fadd_rn(r, __fmul_rn(e, 0.693359375f));
    return r;
}

#define NEON_HORIZ(a0, a1, a2, a3) __fadd_rn(__fadd_rn(a0, a2), __fadd_rn(a1, a3))

// ---------------------------------------------------------------------------
// K1: anchor rows. One thread per b, XLA-CPU op order. (unchanged, passing)
// ---------------------------------------------------------------------------
__global__ __launch_bounds__(256) void k_anchor(const float* __restrict__ anchor) {
    int b = blockIdx.x * blockDim.x + threadIdx.x;
    if (b >= B) return;
    const float4* row = (const float4*)(anchor + b * E);
    float4 vv[16];
    float a0 = 0.f, a1 = 0.f, a2 = 0.f, a3 = 0.f;
    #pragma unroll
    for (int c = 0; c < 16; c++) {
        vv[c] = __ldg(row + c);
        a0 = __fadd_rn(a0, __fadd_rn(vv[c].x, EPS));
        a1 = __fadd_rn(a1, __fadd_rn(vv[c].y, EPS));
        a2 = __fadd_rn(a2, __fadd_rn(vv[c].z, EPS));
        a3 = __fadd_rn(a3, __fadd_rn(vv[c].w, EPS));
    }
    float S = NEON_HORIZ(a0, a1, a2, a3);
    const float* vf = (const float*)vv;
    #pragma unroll
    for (int e = 0; e < E; e++) {
        float a = __fdiv_rn(__fadd_rn(vf[e], EPS), S);
        g_aw[b * E + e] = a;
        g_la[b * E + e] = xla_logf(__fadd_rn(a, EPS));
    }
}

// ---------------------------------------------------------------------------
// K2: confusion scores, occupancy-optimized. One thread per (b,k), 256/CTA,
// two-pass row read: pass 1 sums via asm loads (not CSE-able with pass 2),
// pass 2 re-reads through L1/L2 (row is resident). Arithmetic is op-identical
// to the R5 passing kernel: 4 NEON accumulators + halving horizontal,
// div.rn, xla_logf.
// ---------------------------------------------------------------------------
__global__ __launch_bounds__(256, 5) void k_scores(const float* __restrict__ neg) {
    __shared__ float s_a[E], s_la[E];
    int b = blockIdx.x >> 1;                          // 2 CTAs per batch row
    int k = ((blockIdx.x & 1) << 8) + threadIdx.x;    // 0..511
    if (threadIdx.x < E) {
        s_a[threadIdx.x]  = g_aw[b * E + threadIdx.x];
        s_la[threadIdx.x] = g_la[b * E + threadIdx.x];
    }
    __syncthreads();

    const float4* row = (const float4*)(neg + ((size_t)b * K + k) * E);

    // pass 1: row sum
    float a0 = 0.f, a1 = 0.f, a2 = 0.f, a3 = 0.f;
    #pragma unroll
    for (int c = 0; c < 16; c++) {
        float4 v;
        asm volatile("ld.global.nc.v4.f32 {%0,%1,%2,%3}, [%4];"
                     : "=f"(v.x), "=f"(v.y), "=f"(v.z), "=f"(v.w)
                     : "l"(row + c));
        a0 = __fadd_rn(a0, __fadd_rn(v.x, EPS));
        a1 = __fadd_rn(a1, __fadd_rn(v.y, EPS));
        a2 = __fadd_rn(a2, __fadd_rn(v.z, EPS));
        a3 = __fadd_rn(a3, __fadd_rn(v.w, EPS));
    }
    float S = NEON_HORIZ(a0, a1, a2, a3);

    // pass 2: KL accumulation (4 independent chains per float4 for ILP)
    float k0 = 0.f, k1 = 0.f, k2 = 0.f, k3 = 0.f;
    #pragma unroll 4
    for (int c = 0; c < 16; c++) {
        float4 v = __ldg(row + c);
        int e = 4 * c;
        float nn0 = __fdiv_rn(__fadd_rn(v.x, EPS), S);
        float nn1 = __fdiv_rn(__fadd_rn(v.y, EPS), S);
        float nn2 = __fdiv_rn(__fadd_rn(v.z, EPS), S);
        float nn3 = __fdiv_rn(__fadd_rn(v.w, EPS), S);
        float ln0 = xla_logf(__fadd_rn(nn0, EPS));
        float ln1 = xla_logf(__fadd_rn(nn1, EPS));
        float ln2 = xla_logf(__fadd_rn(nn2, EPS));
        float ln3 = xla_logf(__fadd_rn(nn3, EPS));
        k0 = __fadd_rn(k0, __fmul_rn(s_a[e+0], __fsub_rn(s_la[e+0], ln0)));
        k1 = __fadd_rn(k1, __fmul_rn(s_a[e+1], __fsub_rn(s_la[e+1], ln1)));
        k2 = __fadd_rn(k2, __fmul_rn(s_a[e+2], __fsub_rn(s_la[e+2], ln2)));
        k3 = __fadd_rn(k3, __fmul_rn(s_a[e+3], __fsub_rn(s_la[e+3], ln3)));
    }
    g_scores[b * K + k] = -NEON_HORIZ(k0, k1, k2, k3);
}

// ---------------------------------------------------------------------------
// K3: per-row top-64 via bitonic sort of 512 (desc, ties -> lower index).
// ---------------------------------------------------------------------------
__global__ __launch_bounds__(512) void k_topk(float* __restrict__ out_scores) {
    __shared__ float ss[K];
    __shared__ int   si[K];
    int b = blockIdx.x, tid = threadIdx.x;
    ss[tid] = g_scores[b * K + tid];
    si[tid] = tid;
    for (int sz = 2; sz <= K; sz <<= 1) {
        for (int j = sz >> 1; j > 0; j >>= 1) {
            __syncthreads();
            int ixj = tid ^ j;
            if (ixj > tid) {
                bool desc = ((tid & sz) == 0);
                float s1 = ss[tid], s2 = ss[ixj];
                int   i1 = si[tid], i2 = si[ixj];
                bool g = (s1 > s2) || (s1 == s2 && i1 < i2);
                if (g != desc) {
                    ss[tid] = s2; ss[ixj] = s1;
                    si[tid] = i2; si[ixj] = i1;
                }
            }
        }
    }
    __syncthreads();
    if (tid < TOPK) {
        out_scores[b * TOPK + tid] = ss[tid];
        g_idx[b * TOPK + tid]      = si[tid];
    }
}

// ---------------------------------------------------------------------------
// K4: gather selected candidate rows (769 f32) — coalesced copy. (unchanged)
// ---------------------------------------------------------------------------
__global__ __launch_bounds__(128) void k_gather(
    const float* __restrict__ cand, float* __restrict__ out_hard)
{
    int blk = blockIdx.x;
    int b = blk >> 6, j = blk & (TOPK - 1);
    int idx = g_idx[b * TOPK + j];
    const float* __restrict__ src = cand + ((size_t)b * K + idx) * D;
    float* __restrict__ dst = out_hard + ((size_t)b * TOPK + j) * D;
    #pragma unroll
    for (int i = threadIdx.x; i < D; i += 128)
        dst[i] = __ldg(src + i);
}

// ---------------------------------------------------------------------------
extern "C" void kernel_launch(void* const* d_in, const int* in_sizes, int n_in,
                              void* d_out, int out_size) {
    const float* anchor = (const float*)d_in[0];
    const float* neg    = (const float*)d_in[1];
    const float* cand   = (const float*)d_in[2];
    float* out        = (float*)d_out;
    float* out_hard   = out;
    float* out_scores = out + (size_t)B * TOPK * D;

    k_anchor<<<4, 256>>>(anchor);
    k_scores<<<B * 2, 256>>>(neg);
    k_topk<<<B, 512>>>(out_scores);
    k_gather<<<B * TOPK, 128>>>(cand, out_hard);
}